// round 1
// baseline (speedup 1.0000x reference)
#include <cuda_runtime.h>
#include <cstdint>

// Output: [B=64, SRC_XLEN=16000, D=128] fp32.
// Rows r with (r % 4000) < 1000 get x[b, r % 4000, :]; all other rows are zero.
// One pass: every output float4 written exactly once.

static constexpr int B = 64;
static constexpr int SRC_XLEN = 16000;
static constexpr int D = 128;
static constexpr int L = 1000;
static constexpr int SEG_STRIDE = 4000;          // seg_len * L = 4 * 1000
static constexpr int D4 = D / 4;                 // 32 float4 per row
static constexpr int ROW_SHIFT = 5;              // log2(D4)
static constexpr int PER_BATCH_F4 = SRC_XLEN * D4;   // 512000 float4 per batch

__global__ __launch_bounds__(256) void seg_zero_pad_kernel(
    const float4* __restrict__ x,   // [B, L, D] as float4: [B, L, 32]
    float4* __restrict__ out        // [B, SRC_XLEN, D] as float4
) {
    const int idx = blockIdx.x * blockDim.x + threadIdx.x;   // float4 index within batch
    const int b = blockIdx.y;

    const int row = idx >> ROW_SHIFT;          // 0 .. 15999
    const int d4  = idx & (D4 - 1);            // 0 .. 31

    const int r = row % SEG_STRIDE;            // position within segment stride

    float4 v;
    if (r < L) {
        v = __ldg(&x[(b * L + r) * D4 + d4]);
    } else {
        v = make_float4(0.f, 0.f, 0.f, 0.f);
    }
    out[(size_t)b * PER_BATCH_F4 + idx] = v;
}

extern "C" void kernel_launch(void* const* d_in, const int* in_sizes, int n_in,
                              void* d_out, int out_size) {
    const float4* x = (const float4*)d_in[0];
    float4* out = (float4*)d_out;

    dim3 block(256);
    dim3 grid(PER_BATCH_F4 / 256, B);   // 2000 x 64
    seg_zero_pad_kernel<<<grid, block>>>(x, out);
}

// round 3
// speedup vs baseline: 1.2417x; 1.2417x over previous
#include <cuda_runtime.h>
#include <cstdint>

// Output: [B=64, SRC_XLEN=16000, D=128] fp32.
// Rows r with (r % 4000) < 1000 get x[b, r % 4000, :]; all other rows zero.
//
// Strategy:
//  - Zero rows (3/4 of bytes, 384 MiB): written via TMA bulk stores
//    (cp.async.bulk shared->global) from a zeroed SMEM staging buffer,
//    bypassing the L1tex/LSU per-thread store path.
//  - Data rows (1/4 of bytes): each x float4 loaded ONCE, stored to its
//    4 segment destinations via STG.128.

static constexpr int B = 64;
static constexpr int SRC_XLEN = 16000;
static constexpr int L = 1000;
static constexpr int SEG = 4;
static constexpr int SEG_STRIDE = 4000;        // rows between segment starts
static constexpr int D4 = 32;                  // 128 floats = 32 float4 per row
static constexpr int ROW_BYTES = 512;

static constexpr int CHUNK_ROWS = 60;
static constexpr int CHUNK_BYTES = CHUNK_ROWS * ROW_BYTES;      // 30720
static constexpr int CHUNKS_PER_REGION = 3000 / CHUNK_ROWS;     // 50
static constexpr int N_REGIONS = B * SEG;                       // 256
static constexpr int N_ZERO_BLOCKS = N_REGIONS * CHUNKS_PER_REGION;  // 12800
static constexpr int N_COPY_BLOCKS = (B * L * D4) / 256;        // 8000
static constexpr int N_BLOCKS = N_ZERO_BLOCKS + N_COPY_BLOCKS;  // 20800
// 20800 = 1600 * 13; interleave 5 copy : 8 zero per group of 13.

__global__ __launch_bounds__(256) void seg_zero_pad_kernel(
    const float4* __restrict__ x,   // [B, L, 32] float4
    float4* __restrict__ out        // [B, SRC_XLEN, 32] float4
) {
    __shared__ __align__(128) float4 zbuf[CHUNK_BYTES / 16];   // 30 KiB of zeros

    const int bid = blockIdx.x;
    const int t = threadIdx.x;
    const int grp = bid / 13;
    const int lane = bid % 13;

    if (lane >= 5) {
        // ---------------- zero block: TMA bulk store of 30 KiB zeros ----------------
        const int zid = grp * 8 + (lane - 5);              // 0 .. 12799
        const int region = zid / CHUNKS_PER_REGION;        // 0 .. 255
        const int j = zid - region * CHUNKS_PER_REGION;    // 0 .. 49
        const int batch = region >> 2;
        const int seg = region & 3;

        const size_t dst_off = (size_t)batch * SRC_XLEN * ROW_BYTES
                             + (size_t)(seg * SEG_STRIDE + L) * ROW_BYTES
                             + (size_t)j * CHUNK_BYTES;

        const float4 z = make_float4(0.f, 0.f, 0.f, 0.f);
        #pragma unroll
        for (int i = t; i < CHUNK_BYTES / 16; i += 256) zbuf[i] = z;
        __syncthreads();

        if (t == 0) {
            unsigned long long gptr =
                (unsigned long long)__cvta_generic_to_global((char*)out + dst_off);
            unsigned saddr;
            asm("{ .reg .u64 tmp; cvta.to.shared.u64 tmp, %1; cvt.u32.u64 %0, tmp; }"
                : "=r"(saddr) : "l"(zbuf));
            asm volatile("fence.proxy.async.shared::cta;" ::: "memory");
            asm volatile(
                "cp.async.bulk.global.shared::cta.bulk_group [%0], [%1], %2;"
                :: "l"(gptr), "r"(saddr), "r"((unsigned)CHUNK_BYTES) : "memory");
            asm volatile("cp.async.bulk.commit_group;" ::: "memory");
            asm volatile("cp.async.bulk.wait_group.read 0;" ::: "memory");
        }
    } else {
        // ---------------- copy block: load x once, store to 4 segments ----------------
        const int cid = grp * 5 + lane;                    // 0 .. 7999
        const int gtid = cid * 256 + t;                    // 0 .. 2,047,999
        // x is [B, L, 32] flattened, so gtid indexes it directly.
        const int d4 = gtid & 31;
        const int rowflat = gtid >> 5;                     // batch * L + r
        const int batch = rowflat / L;
        const int r = rowflat - batch * L;

        const float4 v = __ldg(&x[gtid]);
        float4* dst = out + ((size_t)batch * SRC_XLEN + r) * D4 + d4;
        #pragma unroll
        for (int s = 0; s < SEG; s++) {
            dst[(size_t)s * SEG_STRIDE * D4] = v;
        }
    }
}

extern "C" void kernel_launch(void* const* d_in, const int* in_sizes, int n_in,
                              void* d_out, int out_size) {
    const float4* x = (const float4*)d_in[0];
    float4* out = (float4*)d_out;
    seg_zero_pad_kernel<<<N_BLOCKS, 256>>>(x, out);
}